// round 2
// baseline (speedup 1.0000x reference)
#include <cuda_runtime.h>

// out[i] = sum_j S[i][j] * w[j]   (S: [n, n] row-major fp32, w: [n] fp32)
//
// Persistent grid-stride over rows: one launch wave, w stays hot in L1
// across the ~13 rows each CTA handles. S is streamed with __ldcs
// (evict-first) so it doesn't thrash w out of L1.
__global__ void __launch_bounds__(256) rowdot_persistent_kernel(
    const float* __restrict__ S,
    const float* __restrict__ w,
    float* __restrict__ out,
    int n)
{
    const int n4 = n >> 2;            // float4 elements per row (4096)
    const int bd = blockDim.x;        // 256
    const float4* __restrict__ w4 = reinterpret_cast<const float4*>(w);

    const int lane = threadIdx.x & 31;
    const int wid  = threadIdx.x >> 5;
    __shared__ float warp_sums[8];

    for (int row = blockIdx.x; row < n; row += gridDim.x) {
        const float4* __restrict__ s4 =
            reinterpret_cast<const float4*>(S + (size_t)row * n);

        float a0 = 0.0f, a1 = 0.0f, a2 = 0.0f, a3 = 0.0f;

        // 4096 float4 / 256 threads = 16 per thread; unroll x4 so each
        // step issues 4 independent LDG.128 of S (front-batched → MLP≈4+)
        // plus 4 w loads that hit L1.
        for (int i = threadIdx.x; i < n4; i += 4 * bd) {
            float4 sa = __ldcs(&s4[i]);
            float4 sb = __ldcs(&s4[i +     bd]);
            float4 sc = __ldcs(&s4[i + 2 * bd]);
            float4 sd = __ldcs(&s4[i + 3 * bd]);
            float4 wa = __ldg(&w4[i]);
            float4 wb = __ldg(&w4[i +     bd]);
            float4 wc = __ldg(&w4[i + 2 * bd]);
            float4 wd = __ldg(&w4[i + 3 * bd]);

            a0 = fmaf(sa.x, wa.x, a0); a0 = fmaf(sa.y, wa.y, a0);
            a0 = fmaf(sa.z, wa.z, a0); a0 = fmaf(sa.w, wa.w, a0);
            a1 = fmaf(sb.x, wb.x, a1); a1 = fmaf(sb.y, wb.y, a1);
            a1 = fmaf(sb.z, wb.z, a1); a1 = fmaf(sb.w, wb.w, a1);
            a2 = fmaf(sc.x, wc.x, a2); a2 = fmaf(sc.y, wc.y, a2);
            a2 = fmaf(sc.z, wc.z, a2); a2 = fmaf(sc.w, wc.w, a2);
            a3 = fmaf(sd.x, wd.x, a3); a3 = fmaf(sd.y, wd.y, a3);
            a3 = fmaf(sd.z, wd.z, a3); a3 = fmaf(sd.w, wd.w, a3);
        }

        float acc = (a0 + a1) + (a2 + a3);

        // Warp reduce
        #pragma unroll
        for (int off = 16; off > 0; off >>= 1)
            acc += __shfl_down_sync(0xFFFFFFFFu, acc, off);

        // Block reduce (8 warps). First sync guards warp_sums reuse
        // from the previous row iteration.
        __syncthreads();
        if (lane == 0) warp_sums[wid] = acc;
        __syncthreads();

        if (wid == 0) {
            float v = (lane < 8) ? warp_sums[lane] : 0.0f;
            #pragma unroll
            for (int off = 4; off > 0; off >>= 1)
                v += __shfl_down_sync(0xFFFFFFFFu, v, off);
            if (lane == 0) out[row] = v;
        }
    }
}

extern "C" void kernel_launch(void* const* d_in, const int* in_sizes, int n_in,
                              void* d_out, int out_size) {
    const float* S = (const float*)d_in[0];
    const float* w = (const float*)d_in[1];
    float* out = (float*)d_out;

    const int n = in_sizes[1];  // weights length = N = 16384

    // One persistent wave: 8 CTAs/SM x 152 SMs (GB300). Grid-stride handles
    // any SM-count mismatch.
    const int grid = 1216;
    rowdot_persistent_kernel<<<grid, 256>>>(S, w, out, n);
}

// round 3
// speedup vs baseline: 1.0788x; 1.0788x over previous
#include <cuda_runtime.h>

// out[i] = sum_j S[i][j] * w[j]   (S: [n,n] row-major fp32, w: [n] fp32)
// One CTA per row, 256 threads. S streamed with evict-first (__ldcs);
// w cached normally (hot in L2/L1 after first wave). 2-way accumulator
// split for load batching while keeping regs low (occupancy is king).
__global__ void __launch_bounds__(256) rowdot_kernel(
    const float* __restrict__ S,
    const float* __restrict__ w,
    float* __restrict__ out,
    int n)
{
    const int row = blockIdx.x;
    const float4* __restrict__ s4 = reinterpret_cast<const float4*>(S + (size_t)row * n);
    const float4* __restrict__ w4 = reinterpret_cast<const float4*>(w);

    const int n4 = n >> 2;        // 4096 float4 per row
    const int bd = blockDim.x;    // 256

    float a0 = 0.0f, a1 = 0.0f;

    // 16 iterations/thread -> 8 unrolled steps of 2 independent LDG.128.
    int i = threadIdx.x;
    for (; i + bd < n4; i += 2 * bd) {
        float4 sa = __ldcs(&s4[i]);
        float4 sb = __ldcs(&s4[i + bd]);
        float4 wa = __ldg(&w4[i]);
        float4 wb = __ldg(&w4[i + bd]);

        a0 = fmaf(sa.x, wa.x, a0); a0 = fmaf(sa.y, wa.y, a0);
        a0 = fmaf(sa.z, wa.z, a0); a0 = fmaf(sa.w, wa.w, a0);
        a1 = fmaf(sb.x, wb.x, a1); a1 = fmaf(sb.y, wb.y, a1);
        a1 = fmaf(sb.z, wb.z, a1); a1 = fmaf(sb.w, wb.w, a1);
    }
    if (i < n4) {  // n4 = 4096 is a multiple of 512 so this never fires, but keep it safe
        float4 sa = __ldcs(&s4[i]);
        float4 wa = __ldg(&w4[i]);
        a0 = fmaf(sa.x, wa.x, a0); a0 = fmaf(sa.y, wa.y, a0);
        a0 = fmaf(sa.z, wa.z, a0); a0 = fmaf(sa.w, wa.w, a0);
    }

    float acc = a0 + a1;

    // Warp reduce
    #pragma unroll
    for (int off = 16; off > 0; off >>= 1)
        acc += __shfl_down_sync(0xFFFFFFFFu, acc, off);

    // Block reduce across 8 warps
    __shared__ float warp_sums[8];
    const int lane = threadIdx.x & 31;
    const int wid  = threadIdx.x >> 5;
    if (lane == 0) warp_sums[wid] = acc;
    __syncthreads();

    if (wid == 0) {
        float v = (lane < 8) ? warp_sums[lane] : 0.0f;
        #pragma unroll
        for (int off = 4; off > 0; off >>= 1)
            v += __shfl_down_sync(0xFFFFFFFFu, v, off);
        if (lane == 0) out[row] = v;
    }
}

extern "C" void kernel_launch(void* const* d_in, const int* in_sizes, int n_in,
                              void* d_out, int out_size) {
    const float* S = (const float*)d_in[0];
    const float* w = (const float*)d_in[1];
    float* out = (float*)d_out;

    const int n = in_sizes[1];  // N = 16384

    rowdot_kernel<<<n, 256>>>(S, w, out, n);
}

// round 4
// speedup vs baseline: 1.1229x; 1.0408x over previous
#include <cuda_runtime.h>

// out[i] = sum_j S[i][j] * w[j]   (S: [n,n] row-major fp32, w: [n] fp32)
// One CTA per row, 256 threads, Blackwell 256-bit loads (LDG.E.256).
// Warp covers 8KB per load instruction pair; 8 iterations/thread at n=16384.

__device__ __forceinline__ void ldg_v8(const float* __restrict__ p,
                                       float& a0, float& a1, float& a2, float& a3,
                                       float& a4, float& a5, float& a6, float& a7)
{
    asm volatile("ld.global.v8.f32 {%0,%1,%2,%3,%4,%5,%6,%7}, [%8];"
        : "=f"(a0), "=f"(a1), "=f"(a2), "=f"(a3),
          "=f"(a4), "=f"(a5), "=f"(a6), "=f"(a7)
        : "l"(p));
}

__global__ void __launch_bounds__(256) rowdot_v8_kernel(
    const float* __restrict__ S,
    const float* __restrict__ w,
    float* __restrict__ out,
    int n)
{
    const int row = blockIdx.x;
    const float* __restrict__ srow = S + (size_t)row * n;

    const int n8 = n >> 3;      // 2048 float8 chunks per row
    const int bd = blockDim.x;  // 256 -> 8 iterations per thread

    float acc0 = 0.0f, acc1 = 0.0f;

    for (int i = threadIdx.x; i < n8; i += bd) {
        float s0, s1, s2, s3, s4, s5, s6, s7;
        float w0, w1, w2, w3, w4, w5, w6, w7;
        ldg_v8(srow + (size_t)i * 8, s0, s1, s2, s3, s4, s5, s6, s7);
        ldg_v8(w    + (size_t)i * 8, w0, w1, w2, w3, w4, w5, w6, w7);

        acc0 = fmaf(s0, w0, acc0);
        acc1 = fmaf(s1, w1, acc1);
        acc0 = fmaf(s2, w2, acc0);
        acc1 = fmaf(s3, w3, acc1);
        acc0 = fmaf(s4, w4, acc0);
        acc1 = fmaf(s5, w5, acc1);
        acc0 = fmaf(s6, w6, acc0);
        acc1 = fmaf(s7, w7, acc1);
    }

    float acc = acc0 + acc1;

    // Warp reduce
    #pragma unroll
    for (int off = 16; off > 0; off >>= 1)
        acc += __shfl_down_sync(0xFFFFFFFFu, acc, off);

    // Block reduce across 8 warps
    __shared__ float warp_sums[8];
    const int lane = threadIdx.x & 31;
    const int wid  = threadIdx.x >> 5;
    if (lane == 0) warp_sums[wid] = acc;
    __syncthreads();

    if (wid == 0) {
        float v = (lane < 8) ? warp_sums[lane] : 0.0f;
        #pragma unroll
        for (int off = 4; off > 0; off >>= 1)
            v += __shfl_down_sync(0xFFFFFFFFu, v, off);
        if (lane == 0) out[row] = v;
    }
}

extern "C" void kernel_launch(void* const* d_in, const int* in_sizes, int n_in,
                              void* d_out, int out_size) {
    const float* S = (const float*)d_in[0];
    const float* w = (const float*)d_in[1];
    float* out = (float*)d_out;

    const int n = in_sizes[1];  // N = 16384

    rowdot_v8_kernel<<<n, 256>>>(S, w, out, n);
}